// round 7
// baseline (speedup 1.0000x reference)
#include <cuda_runtime.h>
#include <cstdint>

// Masked row-wise cumsum: out[r,:] = cumsum(x[r,:] * mask[r,:])
// x: f32 [4096, 32768]; mask: 4-byte 0/1 words on the wire (byte fallback
// kept); out: f32 [4096, 32768].
//
// Single-pass decoupled tile scan: each row split into 16 tiles of 2048,
// one CTA per tile (grid=65536, 512 threads, 4 CTAs/SM). Every CTA loads its
// tile immediately -> input traffic is fully wave-parallel (no serial chunk
// loop). Cross-tile prefix: each tile publishes its aggregate via one
// relaxed 8-byte store; a tile's <=15 predecessors are read by one
// warp-parallel spin (lane k watches predecessor t-1-k) + fixed butterfly
// reduce => deterministic exclusive prefix, no serial lookback chain.
// Tile-state array re-zeroed by an init kernel each launch.

#ifndef CUMSUM_N
#define CUMSUM_N 32768
#endif

#define TPB   512
#define VEC   4
#define TILE  (TPB * VEC)          // 2048
#define TPR   (CUMSUM_N / TILE)    // 16 tiles per row
#define NWARP (TPB / 32)           // 16

#define MAX_TILES 65536            // 4096 rows * 16 tiles

// per-tile state: 0 = not ready; else (1ull<<32) | f32_bits(aggregate)
__device__ unsigned long long g_tile_state[MAX_TILES];

__device__ __forceinline__ void st_relaxed_u64(unsigned long long* p,
                                               unsigned long long v)
{
    asm volatile("st.relaxed.gpu.global.u64 [%0], %1;" :: "l"(p), "l"(v) : "memory");
}

__device__ __forceinline__ unsigned long long ld_relaxed_u64(
    const unsigned long long* p)
{
    unsigned long long v;
    asm volatile("ld.relaxed.gpu.global.u64 %0, [%1];" : "=l"(v) : "l"(p) : "memory");
    return v;
}

__global__ void init_state_kernel(int n)
{
    const int i = blockIdx.x * blockDim.x + threadIdx.x;
    if (i < n) g_tile_state[i] = 0ull;
}

__global__ __launch_bounds__(TPB, 4)
void masked_cumsum_tile_kernel(const float* __restrict__ x,
                               const void* __restrict__ mask,
                               float* __restrict__ out)
{
    const int bid  = blockIdx.x;
    const int t    = bid & (TPR - 1);       // tile index within row
    const int tid  = threadIdx.x;
    const int lane = tid & 31;
    const int wid  = tid >> 5;

    const size_t off = (size_t)bid * TILE + (size_t)tid * VEC;

    // --- per-warp mask dtype detection (deterministic, no barrier) ---
    const unsigned probe = ((const unsigned*)mask)[lane];
    const bool clean = (probe == 0u) | (probe == 1u) | (probe == 0x3F800000u);
    const bool word_mode = __all_sync(0xffffffffu, clean);

    // ---- load + mask (issued immediately at CTA start) ----
    const float4 xv = __ldcs(reinterpret_cast<const float4*>(x + off));

    float v0, v1, v2, v3;
    if (word_mode) {
        const uint4 mv = __ldcs(reinterpret_cast<const uint4*>((const unsigned*)mask + off));
        v0 = mv.x ? xv.x : 0.f;
        v1 = mv.y ? xv.y : 0.f;
        v2 = mv.z ? xv.z : 0.f;
        v3 = mv.w ? xv.w : 0.f;
    } else {
        const unsigned mv = __ldcs(reinterpret_cast<const unsigned*>((const uint8_t*)mask + off));
        v0 = (mv & 0x000000FFu) ? xv.x : 0.f;
        v1 = (mv & 0x0000FF00u) ? xv.y : 0.f;
        v2 = (mv & 0x00FF0000u) ? xv.z : 0.f;
        v3 = (mv & 0xFF000000u) ? xv.w : 0.f;
    }

    // ---- thread-local inclusive scan of 4 ----
    const float s0 = v0;
    const float s1 = s0 + v1;
    const float s2 = s1 + v2;
    const float s3 = s2 + v3;

    // ---- warp inclusive scan of per-thread totals ----
    float tsc = s3;
    #pragma unroll
    for (int d = 1; d < 32; d <<= 1) {
        float nv = __shfl_up_sync(0xffffffffu, tsc, d);
        if (lane >= d) tsc += nv;
    }
    const float thread_excl = tsc - s3;

    __shared__ float s_warp[NWARP];
    __shared__ float s_excl;

    if (lane == 31) s_warp[wid] = tsc;
    __syncthreads();                         // barrier #1

    // ---- every warp redundantly scans the 16 warp totals ----
    float wincl = (lane < NWARP) ? s_warp[lane] : 0.f;
    #pragma unroll
    for (int d = 1; d < NWARP; d <<= 1) {
        float nv = __shfl_up_sync(0xffffffffu, wincl, d);
        if (lane >= d) wincl += nv;
    }
    const float warp_excl = (wid == 0)
        ? 0.f
        : __shfl_sync(0xffffffffu, wincl, wid - 1);
    const float block_tot = __shfl_sync(0xffffffffu, wincl, NWARP - 1);

    // ---- publish aggregate + warp-parallel wait for predecessors ----
    if (wid == 0) {
        if (lane == 0) {
            const unsigned long long packed =
                (1ull << 32) | (unsigned long long)__float_as_uint(block_tot);
            st_relaxed_u64(&g_tile_state[bid], packed);
        }

        float agg = 0.f;
        if (lane < t) {
            const unsigned long long* pred = &g_tile_state[bid - 1 - lane];
            unsigned long long v = ld_relaxed_u64(pred);
            while (v == 0ull) {
                __nanosleep(40);
                v = ld_relaxed_u64(pred);
            }
            agg = __uint_as_float((unsigned)v);
        }

        // fixed butterfly reduce (deterministic association across replays)
        #pragma unroll
        for (int d = 16; d > 0; d >>= 1)
            agg += __shfl_xor_sync(0xffffffffu, agg, d);

        if (lane == 0) s_excl = agg;
    }
    __syncthreads();                         // barrier #2

    const float offv = s_excl + warp_excl + thread_excl;

    float4 o;
    o.x = s0 + offv;
    o.y = s1 + offv;
    o.z = s2 + offv;
    o.w = s3 + offv;
    __stcs(reinterpret_cast<float4*>(out + off), o);
}

extern "C" void kernel_launch(void* const* d_in, const int* in_sizes, int n_in,
                              void* d_out, int out_size)
{
    const float* x    = (const float*)d_in[0];
    const void*  mask = d_in[1];
    float*       out  = (float*)d_out;

    const int n_rows  = in_sizes[0] / CUMSUM_N;   // 4096
    const int n_tiles = n_rows * TPR;             // 65536

    init_state_kernel<<<(n_tiles + 1023) / 1024, 1024>>>(n_tiles);
    masked_cumsum_tile_kernel<<<n_tiles, TPB>>>(x, mask, out);
}

// round 8
// speedup vs baseline: 2.3987x; 2.3987x over previous
#include <cuda_runtime.h>
#include <cstdint>

// Masked row-wise cumsum: out[r,:] = cumsum(x[r,:] * mask[r,:])
// x: f32 [4096, 32768]; mask: 4-byte 0/1 words on the wire (byte fallback
// kept); out: f32 [4096, 32768].
//
// R5 shape (1 CTA/row, 512 thr, 2048-elem chunks, 4 CTAs/SM) + cp.async
// (LDGSTS) double-buffered prefetch: next chunk's x+mask stream into SMEM
// with zero register cost while the current chunk scans. Each thread copies
// and reads ONLY its own 16B slices -> visibility via its own
// cp.async.wait_group; the single per-chunk __syncthreads (warp totals,
// ping-ponged) remains the only barrier.

#ifndef CUMSUM_N
#define CUMSUM_N 32768
#endif

#define TPB   512
#define VEC   4
#define CHUNK (TPB * VEC)   // 2048
#define NWARP (TPB / 32)    // 16

__device__ __forceinline__ unsigned smem_u32(const void* p)
{
    unsigned a;
    asm("{ .reg .u64 t; cvta.to.shared.u64 t, %1; cvt.u32.u64 %0, t; }"
        : "=r"(a) : "l"(p));
    return a;
}

__device__ __forceinline__ void cp_async16(unsigned dst, const void* src)
{
    asm volatile("cp.async.cg.shared.global [%0], [%1], 16;"
                 :: "r"(dst), "l"(src) : "memory");
}

__device__ __forceinline__ void cp_async4(unsigned dst, const void* src)
{
    asm volatile("cp.async.ca.shared.global [%0], [%1], 4;"
                 :: "r"(dst), "l"(src) : "memory");
}

__device__ __forceinline__ void cp_commit()
{
    asm volatile("cp.async.commit_group;" ::: "memory");
}

__device__ __forceinline__ void cp_wait1()
{
    asm volatile("cp.async.wait_group 1;" ::: "memory");
}

__global__ __launch_bounds__(TPB, 4)
void masked_cumsum_row_kernel(const float* __restrict__ x,
                              const void* __restrict__ mask,
                              float* __restrict__ out,
                              int n_cols)
{
    const int row  = blockIdx.x;
    const size_t base = (size_t)row * (size_t)n_cols;

    const int tid  = threadIdx.x;
    const int lane = tid & 31;
    const int wid  = tid >> 5;

    // --- per-warp mask dtype detection (deterministic, no barrier) ---
    const unsigned probe = ((const unsigned*)mask)[lane];
    const bool clean = (probe == 0u) | (probe == 1u) | (probe == 0x3F800000u);
    const bool word_mode = __all_sync(0xffffffffu, clean);

    __shared__ float4 s_x[2][TPB];    // 16 KB
    __shared__ uint4  s_m[2][TPB];    // 16 KB (byte mode uses first 2 KB/stage)
    __shared__ float  s_warp[2][NWARP];

    const unsigned sx0 = smem_u32(&s_x[0][tid]);
    const unsigned sx1 = smem_u32(&s_x[1][tid]);
    const unsigned sm0 = smem_u32(&s_m[0][tid]);
    const unsigned sm1 = smem_u32(&s_m[1][tid]);
    const unsigned smb0 = smem_u32(&s_m[0][0]) + tid * 4;   // byte-mode slice
    const unsigned smb1 = smem_u32(&s_m[1][0]) + tid * 4;

    const int nch = n_cols / CHUNK;   // 16

    // ---- prologue: prefetch chunks 0 and 1 ----
    {
        const size_t off0 = base + (size_t)tid * VEC;
        const size_t off1 = off0 + CHUNK;
        cp_async16(sx0, x + off0);
        if (word_mode) cp_async16(sm0, (const unsigned*)mask + off0);
        else           cp_async4(smb0, (const uint8_t*)mask + off0);
        cp_commit();
        cp_async16(sx1, x + off1);
        if (word_mode) cp_async16(sm1, (const unsigned*)mask + off1);
        else           cp_async4(smb1, (const uint8_t*)mask + off1);
        cp_commit();
    }

    float carry = 0.0f;

    #pragma unroll 1
    for (int c = 0; c < nch; c++) {
        const int p = c & 1;
        const size_t off = base + (size_t)c * CHUNK + (size_t)tid * VEC;

        cp_wait1();   // this thread's chunk-c slices have landed

        const float4 xv = s_x[p][tid];

        float v0, v1, v2, v3;
        if (word_mode) {
            const uint4 mv = s_m[p][tid];
            v0 = mv.x ? xv.x : 0.f;
            v1 = mv.y ? xv.y : 0.f;
            v2 = mv.z ? xv.z : 0.f;
            v3 = mv.w ? xv.w : 0.f;
        } else {
            const unsigned mv =
                *reinterpret_cast<const unsigned*>(
                    reinterpret_cast<const uint8_t*>(&s_m[p][0]) + tid * 4);
            v0 = (mv & 0x000000FFu) ? xv.x : 0.f;
            v1 = (mv & 0x0000FF00u) ? xv.y : 0.f;
            v2 = (mv & 0x00FF0000u) ? xv.z : 0.f;
            v3 = (mv & 0xFF000000u) ? xv.w : 0.f;
        }

        // ---- refill buffer p with chunk c+2 (own slice only; values above
        //      are already consumed into registers) ----
        if (c + 2 < nch) {
            const size_t noff = off + 2 * (size_t)CHUNK;
            cp_async16(p ? sx1 : sx0, x + noff);
            if (word_mode) cp_async16(p ? sm1 : sm0, (const unsigned*)mask + noff);
            else           cp_async4(p ? smb1 : smb0, (const uint8_t*)mask + noff);
        }
        cp_commit();   // keep group accounting uniform

        // ---- thread-local inclusive scan of 4 ----
        const float s0 = v0;
        const float s1 = s0 + v1;
        const float s2 = s1 + v2;
        const float s3 = s2 + v3;

        // ---- warp inclusive scan of per-thread totals ----
        float t = s3;
        #pragma unroll
        for (int d = 1; d < 32; d <<= 1) {
            float nv = __shfl_up_sync(0xffffffffu, t, d);
            if (lane >= d) t += nv;
        }
        const float thread_excl = t - s3;

        if (lane == 31) s_warp[p][wid] = t;
        __syncthreads();                      // the ONLY barrier per chunk

        // ---- every warp redundantly scans the 16 warp totals ----
        float wincl = (lane < NWARP) ? s_warp[p][lane] : 0.f;
        #pragma unroll
        for (int d = 1; d < NWARP; d <<= 1) {
            float nv = __shfl_up_sync(0xffffffffu, wincl, d);
            if (lane >= d) wincl += nv;
        }
        const float warp_excl = (wid == 0)
            ? 0.f
            : __shfl_sync(0xffffffffu, wincl, wid - 1);
        const float block_tot = __shfl_sync(0xffffffffu, wincl, NWARP - 1);

        const float offv = carry + warp_excl + thread_excl;

        float4 o;
        o.x = s0 + offv;
        o.y = s1 + offv;
        o.z = s2 + offv;
        o.w = s3 + offv;
        __stcs(reinterpret_cast<float4*>(out + off), o);

        carry += block_tot;
    }
}

extern "C" void kernel_launch(void* const* d_in, const int* in_sizes, int n_in,
                              void* d_out, int out_size)
{
    const float* x    = (const float*)d_in[0];
    const void*  mask = d_in[1];
    float*       out  = (float*)d_out;

    const int n_cols = CUMSUM_N;
    const int n_rows = in_sizes[0] / n_cols;   // 4096

    masked_cumsum_row_kernel<<<n_rows, TPB>>>(x, mask, out, n_cols);
}